// round 9
// baseline (speedup 1.0000x reference)
#include <cuda_runtime.h>
#include <cuda_fp16.h>
#include <cstdint>

// FeedForwardQuantum — R8: GEMM1 hoisted to a precompute kernel.
//   q = cos(x[:, :NQ] + theta)                     (qcos_kernel -> g_q)
//   h = relu([q,1,0..] @ W1e^T)  -> g_h            (hgen_kernel, tensor cores,
//                                                   stored in SMEM-tile image format)
//   out = h @ W2^T + b2                            (ffn_kernel, pure fp16 GEMM2)
// GEMM2: M=16384, N=1024, K=4096. BM=128, BN=128, BK=64, 256 thr, warp tile 32x64.
// Tile rows are 160 B (128 B data + 32 B pad): the odd stride IS the bank swizzle
// (all LDS.64 2-phase, STS.32 2-phase). A and B tiles arrive via cp.async from
// pre-packed images; the main loop is cp + LDS.64 + MMA only.

#define NQ      10
#define BM      128
#define BN      128
#define BK      64
#define THREADS 256
#define E_DIM   1024
#define K_DIM   4096
#define NCHUNK  (K_DIM / BK)       // 64
#define ROWB    160                // bytes per tile row (128 data + 32 pad)
#define STAGE   (128 * ROWB)       // 20480 B per tile stage
#define SM_TOTAL (4 * STAGE)       // A0 A1 B0 B1 = 81920

__device__ float g_q[32768 * NQ];                         // 1.25 MB
__device__ uint4 g_h[(size_t)NCHUNK * 128 * (STAGE/16)];  // [kci][mb][1280], 168 MB
__device__ uint4 g_w2h[NCHUNK * 8 * (STAGE/16)];          // [kci][nb][1280], 10.5 MB

// ---------------- helpers ----------------
__device__ __forceinline__ uint32_t smem_u32(const void* p) {
    uint32_t a;
    asm("{ .reg .u64 t; cvta.to.shared.u64 t, %1; cvt.u32.u64 %0, t; }" : "=r"(a) : "l"(p));
    return a;
}
__device__ __forceinline__ void cp16(uint32_t dst, const void* src) {
    asm volatile("cp.async.cg.shared.global [%0], [%1], 16;" :: "r"(dst), "l"(src) : "memory");
}
__device__ __forceinline__ uint32_t pack_h2(float lo, float hi) {
    __half2 h = __floats2half2_rn(lo, hi);
    return *(uint32_t*)&h;
}

#define MMA_F16(d, a0, a1, a2, a3, b0, b1)                              \
    asm volatile(                                                       \
        "mma.sync.aligned.m16n8k16.row.col.f32.f16.f16.f32 "            \
        "{%0,%1,%2,%3}, {%4,%5,%6,%7}, {%8,%9}, {%0,%1,%2,%3};"         \
        : "+f"((d)[0]), "+f"((d)[1]), "+f"((d)[2]), "+f"((d)[3])        \
        : "r"(a0), "r"(a1), "r"(a2), "r"(a3), "r"(b0), "r"(b1))

// ---------------- prep kernels ----------------
__global__ void qcos_kernel(const float* __restrict__ x,
                            const float* __restrict__ theta, int M, int E) {
    int t = blockIdx.x * blockDim.x + threadIdx.x;
    if (t >= M) return;
    const float* xr = x + (size_t)t * E;
#pragma unroll
    for (int i = 0; i < NQ; i++) g_q[t * NQ + i] = cosf(xr[i] + __ldg(theta + i));
}

// h generator: CTA (kci, mb) computes h rows mb*128..+127, k-cols kci*64..+63,
// emits the pair-packed stride-160 tile image to g_h[kci][mb].
// Pair mapping: k-pair kp (half2 of h-cols 2kp,2kp+1), pairs (kp, kp+4) adjacent:
//   gi = (kp>>3)*4 + (kp&3), slot = (kp>>2)&1, byte = row*160 + gi*8 + slot*4.
__global__ void __launch_bounds__(THREADS)
hgen_kernel(const float* __restrict__ W1, const float* __restrict__ b1v) {
    __shared__ __align__(16) uint32_t img[STAGE / 4];
    const int kci = blockIdx.x;
    const int mb  = blockIdx.y;
    const int tid = threadIdx.x;
    const int warp = tid >> 5, lane = tid & 31;
    const int g = lane >> 2, tg = lane & 3;

    // A fragments (rows mb*128 + 16*warp + g, +8), K=16: [q0..q9, 1, 0...]
    uint32_t qf[4];
    {
        const float* q0 = g_q + (size_t)(mb * 128 + 16 * warp + g) * NQ;
        const float* q1 = q0 + 8 * NQ;
        float2 v0 = *(const float2*)(q0 + 2 * tg);
        float2 v1 = *(const float2*)(q1 + 2 * tg);
        qf[0] = pack_h2(v0.x, v0.y);
        qf[1] = pack_h2(v1.x, v1.y);
        if (tg == 0) {
            float2 w0 = *(const float2*)(q0 + 8);
            float2 w1 = *(const float2*)(q1 + 8);
            qf[2] = pack_h2(w0.x, w0.y);
            qf[3] = pack_h2(w1.x, w1.y);
        } else if (tg == 1) {
            qf[2] = pack_h2(1.f, 0.f);
            qf[3] = qf[2];
        } else {
            qf[2] = 0u; qf[3] = 0u;
        }
    }

#pragma unroll
    for (int j = 0; j < 8; j++) {
        const int row = kci * 64 + 8 * j + g;            // W1e row = h col group
        float2 w01 = *(const float2*)(W1 + (size_t)row * NQ + 2 * tg);
        uint32_t b0 = pack_h2(w01.x, w01.y);
        uint32_t b1r;
        if (tg == 0) {
            float2 w89 = *(const float2*)(W1 + (size_t)row * NQ + 8);
            b1r = pack_h2(w89.x, w89.y);
        } else if (tg == 1) {
            b1r = pack_h2(b1v[row], 0.f);
        } else b1r = 0u;

        float ga[4] = {0.f, 0.f, 0.f, 0.f};
        MMA_F16(ga, qf[0], qf[1], qf[2], qf[3], b0, b1r);

        const int m0  = 16 * warp + g;
        const int gi  = (j >> 1) * 4 + tg;
        const int off = m0 * ROWB + gi * 8 + (j & 1) * 4;   // bytes
        img[off >> 2]                = pack_h2(fmaxf(ga[0], 0.f), fmaxf(ga[1], 0.f));
        img[(off + 8 * ROWB) >> 2]   = pack_h2(fmaxf(ga[2], 0.f), fmaxf(ga[3], 0.f));
    }
    __syncthreads();

    uint4* dst = g_h + ((size_t)kci * 128 + mb) * (STAGE / 16) + tid * 5;
    const uint4* src = (const uint4*)img + tid * 5;
#pragma unroll
    for (int i = 0; i < 5; i++) dst[i] = src[i];
}

// W2 image: g_w2h[(kci*8+nb)*1280 + u] = 16-B unit u of the stride-160 tile image.
__global__ void prep_w2_kernel(const float* __restrict__ W2) {
    int id = blockIdx.x * blockDim.x + threadIdx.x;      // 655360
    if (id >= NCHUNK * 8 * (STAGE / 16)) return;
    const int u   = id % (STAGE / 16);
    const int nb  = (id / (STAGE / 16)) & 7;
    const int kci = id / ((STAGE / 16) * 8);
    const int o     = u * 16;
    const int n_loc = o / ROWB;
    const int rem   = o - n_loc * ROWB;
    uint4 outv = {0u, 0u, 0u, 0u};
    if (rem < 128) {
        const int gi0 = rem >> 3;                        // even
        const float* base = W2 + (size_t)(nb * 128 + n_loc) * K_DIM + kci * 64;
        const int kpa = ((gi0 >> 2) << 3) + (gi0 & 3);
        const int kpb = (((gi0 + 1) >> 2) << 3) + ((gi0 + 1) & 3);
        outv.x = pack_h2(base[2 * kpa],     base[2 * kpa + 1]);
        outv.y = pack_h2(base[2 * kpa + 8], base[2 * kpa + 9]);
        outv.z = pack_h2(base[2 * kpb],     base[2 * kpb + 1]);
        outv.w = pack_h2(base[2 * kpb + 8], base[2 * kpb + 9]);
    }
    g_w2h[id] = outv;
}

// ---------------- main kernel: pure GEMM2 ----------------
__global__ void __launch_bounds__(THREADS, 2)
ffn_kernel(const float* __restrict__ b2, float* __restrict__ out) {
    extern __shared__ __align__(128) char smem[];        // [A0][A1][B0][B1]
    char* Asm = smem;
    char* Bsm = smem + 2 * STAGE;
    const uint32_t as_u32 = smem_u32(Asm);
    const uint32_t bs_u32 = smem_u32(Bsm);

    const int tid  = threadIdx.x;
    const int warp = tid >> 5;
    const int lane = tid & 31;
    const int g    = lane >> 2;
    const int tg   = lane & 3;
    const int nb   = blockIdx.x;                         // n-block fastest: 8 columns
    const int mb   = blockIdx.y;                         //   of one m-block co-resident
    const int wm   = (warp & 3) * 32;
    const int wn   = (warp >> 2) * 64;

    const uint4* aSrc0 = g_h   + ((size_t)0 * 128 + mb) * (STAGE / 16) + tid * 5;
    const uint4* bSrc0 = g_w2h + ((size_t)0 * 8   + nb) * (STAGE / 16) + tid * 5;
    const size_t aStep = (size_t)128 * (STAGE / 16);     // per-chunk stride (uint4)
    const size_t bStep = (size_t)8   * (STAGE / 16);

    // prologue: stage chunk 0 into stage 0
    {
        const uint32_t ad = as_u32 + tid * 80u;
        const uint32_t bd = bs_u32 + tid * 80u;
#pragma unroll
        for (int i = 0; i < 5; i++) cp16(ad + 16u * i, aSrc0 + i);
#pragma unroll
        for (int i = 0; i < 5; i++) cp16(bd + 16u * i, bSrc0 + i);
        asm volatile("cp.async.commit_group;" ::: "memory");
    }

    float acc[2][8][4];
#pragma unroll
    for (int mi = 0; mi < 2; mi++)
#pragma unroll
        for (int ni = 0; ni < 8; ni++)
#pragma unroll
            for (int v = 0; v < 4; v++) acc[mi][ni][v] = 0.f;

    for (int kci = 0; kci < NCHUNK; kci++) {
        const int s = kci & 1;

        asm volatile("cp.async.wait_group 0;" ::: "memory");
        __syncthreads();   // stage s visible to all; all done reading stage s^1

        if (kci + 1 < NCHUNK) {
            const uint4* aS = aSrc0 + (size_t)(kci + 1) * aStep;
            const uint4* bS = bSrc0 + (size_t)(kci + 1) * bStep;
            const uint32_t ad = as_u32 + (uint32_t)(s ^ 1) * STAGE + tid * 80u;
            const uint32_t bd = bs_u32 + (uint32_t)(s ^ 1) * STAGE + tid * 80u;
#pragma unroll
            for (int i = 0; i < 5; i++) cp16(ad + 16u * i, aS + i);
#pragma unroll
            for (int i = 0; i < 5; i++) cp16(bd + 16u * i, bS + i);
            asm volatile("cp.async.commit_group;" ::: "memory");
        }

        const char* As = Asm + s * STAGE;
        const char* Bs = Bsm + s * STAGE;
#pragma unroll
        for (int kk2 = 0; kk2 < 4; kk2++) {
            const uint32_t gi8 = (uint32_t)(4 * kk2 + tg) * 8u;
            uint2 aLo[2], aHi[2];
#pragma unroll
            for (int mi = 0; mi < 2; mi++) {
                const int r0 = wm + 16 * mi + g;
                aLo[mi] = *(const uint2*)(As + r0 * ROWB + gi8);        // (r0, kp), (r0, kp+4)
                aHi[mi] = *(const uint2*)(As + (r0 + 8) * ROWB + gi8);  // (r0+8, ...)
            }
#pragma unroll
            for (int ni = 0; ni < 8; ni++) {
                const int n = wn + 8 * ni + g;
                const uint2 bv = *(const uint2*)(Bs + n * ROWB + gi8);  // b0=kp, b1=kp+4
                MMA_F16(acc[0][ni], aLo[0].x, aHi[0].x, aLo[0].y, aHi[0].y, bv.x, bv.y);
                MMA_F16(acc[1][ni], aLo[1].x, aHi[1].x, aLo[1].y, aHi[1].y, bv.x, bv.y);
            }
        }
    }

    // epilogue: out = acc + b2
    const int mblk = mb * BM;
    const int nblk = nb * BN;
#pragma unroll
    for (int ni = 0; ni < 8; ni++) {
        const int n0 = nblk + wn + 8 * ni + 2 * tg;
        const float2 bvv = *(const float2*)(b2 + n0);
#pragma unroll
        for (int mi = 0; mi < 2; mi++) {
            const int m0 = mblk + wm + 16 * mi + g;
            float2 o0, o1;
            o0.x = acc[mi][ni][0] + bvv.x;  o0.y = acc[mi][ni][1] + bvv.y;
            o1.x = acc[mi][ni][2] + bvv.x;  o1.y = acc[mi][ni][3] + bvv.y;
            *(float2*)(out + (size_t)m0 * E_DIM + n0)       = o0;
            *(float2*)(out + (size_t)(m0 + 8) * E_DIM + n0) = o1;
        }
    }
}

extern "C" void kernel_launch(void* const* d_in, const int* in_sizes, int n_in,
                              void* d_out, int out_size) {
    const float* x     = (const float*)d_in[0];
    const float* theta = (const float*)d_in[1];
    const float* W1    = (const float*)d_in[2];
    const float* b1v   = (const float*)d_in[3];
    const float* W2    = (const float*)d_in[4];
    const float* b2    = (const float*)d_in[5];
    float* out = (float*)d_out;

    const int E = in_sizes[5];        // 1024
    const int M = in_sizes[0] / E;    // 16384

    qcos_kernel<<<(M + 255) / 256, 256>>>(x, theta, M, E);

    dim3 hgrid(NCHUNK, M / BM);       // (64, 128)
    hgen_kernel<<<hgrid, THREADS>>>(W1, b1v);

    prep_w2_kernel<<<(NCHUNK * 8 * (STAGE / 16) + 255) / 256, 256>>>(W2);

    cudaFuncSetAttribute(ffn_kernel, cudaFuncAttributeMaxDynamicSharedMemorySize, SM_TOTAL);
    dim3 grid(E_DIM / BN, M / BM);    // (8, 128); nb fastest -> h-slab shared in L2
    ffn_kernel<<<grid, THREADS, SM_TOTAL>>>(b2, out);
}